// round 1
// baseline (speedup 1.0000x reference)
#include <cuda_runtime.h>
#include <cstdint>

// Problem constants (shapes fixed by the dataset; N/E re-derived from in_sizes)
#define D_DIM 128
#define O_DIM 128
#define R_DIM 4
#define N_MAX 100000

// Scratch: Y[n, r*O + o] = (x @ W_r)[n, o]   -> [N, R*O] = 204.8 MB
__device__ float g_Y[(size_t)N_MAX * R_DIM * O_DIM];

// ---------------------------------------------------------------------------
// GEMM: per (m-tile, relation r):  Y[m0:m0+128, r*128:(r+1)*128] =
//       x[m0:m0+128, 0:128] @ W[r*128:(r+1)*128, 0:128]
// Classic 128x128 block tile, K chunked by 32, 8x8 microtile per thread.
// ---------------------------------------------------------------------------
#define BM 128
#define BN 128
#define BKC 32

__global__ __launch_bounds__(256, 2)
void gemm_kernel(const float* __restrict__ x, const float* __restrict__ W, int N)
{
    __shared__ float sA[BKC][BM + 1];   // x^T chunk [k][m], padded (conflict-free stores)
    __shared__ float sB[BKC][BN];       // W chunk  [k][n]

    const int r  = blockIdx.y;
    const int m0 = blockIdx.x * BM;
    const float* __restrict__ Wr = W + (size_t)r * D_DIM * O_DIM;  // rows r*128..r*128+127

    const int tid = threadIdx.x;
    const int tr  = (tid / 16) * 8;   // row offset of 8x8 microtile
    const int tc  = (tid % 16) * 8;   // col offset

    float acc[8][8];
#pragma unroll
    for (int i = 0; i < 8; i++)
#pragma unroll
        for (int j = 0; j < 8; j++) acc[i][j] = 0.0f;

    for (int k0 = 0; k0 < D_DIM; k0 += BKC) {
        // Load x[m0+.., k0..k0+32) -> sA[k][m]. 4096 floats, 256 threads, float4 loads.
#pragma unroll
        for (int p = 0; p < 4; ++p) {
            int m_local = (tid >> 3) + p * 32;
            int kq      = (tid & 7);
            int gm      = m0 + m_local;
            float4 v = make_float4(0.f, 0.f, 0.f, 0.f);
            if (gm < N)
                v = *(const float4*)(x + (size_t)gm * D_DIM + k0 + kq * 4);
            sA[kq * 4 + 0][m_local] = v.x;
            sA[kq * 4 + 1][m_local] = v.y;
            sA[kq * 4 + 2][m_local] = v.z;
            sA[kq * 4 + 3][m_local] = v.w;
        }
        // Load W[r*128 + k0 + k][n] -> sB[k][n]. 4096 floats.
#pragma unroll
        for (int p = 0; p < 4; ++p) {
            int kk = (tid >> 5) + p * 8;
            int nq = tid & 31;
            float4 v = *(const float4*)(Wr + (size_t)(k0 + kk) * O_DIM + nq * 4);
            *(float4*)&sB[kk][nq * 4] = v;
        }
        __syncthreads();

#pragma unroll
        for (int k = 0; k < BKC; ++k) {
            float a[8];
#pragma unroll
            for (int i = 0; i < 8; i++) a[i] = sA[k][tr + i];
            float4 b0 = *(const float4*)&sB[k][tc];
            float4 b1 = *(const float4*)&sB[k][tc + 4];
            float b[8] = {b0.x, b0.y, b0.z, b0.w, b1.x, b1.y, b1.z, b1.w};
#pragma unroll
            for (int i = 0; i < 8; i++)
#pragma unroll
                for (int j = 0; j < 8; j++)
                    acc[i][j] = fmaf(a[i], b[j], acc[i][j]);
        }
        __syncthreads();
    }

    // Store to Y[gm, r*128 + tc .. +8]
#pragma unroll
    for (int i = 0; i < 8; i++) {
        int gm = m0 + tr + i;
        if (gm < N) {
            float4* dst = (float4*)(g_Y + (size_t)gm * (R_DIM * O_DIM) + r * O_DIM + tc);
            dst[0] = make_float4(acc[i][0], acc[i][1], acc[i][2], acc[i][3]);
            dst[1] = make_float4(acc[i][4], acc[i][5], acc[i][6], acc[i][7]);
        }
    }
}

// ---------------------------------------------------------------------------
// Scatter: for each relation r, edge e: out[row, :] += val * Y[col, r*128:+128]
// One edge per warp-iteration: 1x float4 gather per lane + 1x red.v4 per lane.
// blockIdx.y = relation -> relations processed roughly sequentially, so the
// 51.2 MB Y-stripe of the active relation stays L2-resident.
// ---------------------------------------------------------------------------
__global__ __launch_bounds__(256)
void scatter_kernel(const int* __restrict__ rows, const int* __restrict__ cols,
                    const float* __restrict__ vals, float* __restrict__ out,
                    int E)
{
    const int r    = blockIdx.y;
    const int lane = threadIdx.x & 31;
    const int warp = (blockIdx.x * blockDim.x + threadIdx.x) >> 5;
    const int nwarps = (gridDim.x * blockDim.x) >> 5;

    const int*   __restrict__ rr = rows + (size_t)r * E;
    const int*   __restrict__ cc = cols + (size_t)r * E;
    const float* __restrict__ vv = vals + (size_t)r * E;
    const float* __restrict__ Yr = g_Y + (size_t)r * O_DIM;

    for (int e = warp; e < E; e += nwarps) {
        int   row = __ldg(rr + e);
        int   col = __ldg(cc + e);
        float v   = __ldg(vv + e);

        float4 p = *(const float4*)(Yr + (size_t)col * (R_DIM * O_DIM) + lane * 4);
        p.x *= v; p.y *= v; p.z *= v; p.w *= v;

        float* dst = out + (size_t)row * O_DIM + lane * 4;
        asm volatile("red.global.add.v4.f32 [%0], {%1, %2, %3, %4};"
                     :: "l"(dst), "f"(p.x), "f"(p.y), "f"(p.z), "f"(p.w)
                     : "memory");
    }
}

// ---------------------------------------------------------------------------
// kernel_launch
// Inputs (metadata order): x[N,128] f32, edge_row[4,E] i32, edge_col[4,E] i32,
//                          edge_val[4,E] f32, W[512,128] f32.  out: [N,128] f32.
// ---------------------------------------------------------------------------
extern "C" void kernel_launch(void* const* d_in, const int* in_sizes, int n_in,
                              void* d_out, int out_size)
{
    const float* x        = (const float*)d_in[0];
    const int*   edge_row = (const int*)  d_in[1];
    const int*   edge_col = (const int*)  d_in[2];
    const float* edge_val = (const float*)d_in[3];
    const float* W        = (const float*)d_in[4];
    float*       out      = (float*)d_out;

    const int N = in_sizes[0] / D_DIM;          // 100000
    const int E = in_sizes[1] / R_DIM;          // 400000

    // out is poisoned; zero it (graph-capturable async memset).
    cudaMemsetAsync(out, 0, (size_t)out_size * sizeof(float), 0);

    // Phase 1: Y = x @ [W_0 | W_1 | W_2 | W_3]
    {
        dim3 grid((N + BM - 1) / BM, R_DIM);
        gemm_kernel<<<grid, 256>>>(x, W, N);
    }

    // Phase 2: edge scatter with vectorized f32 reductions.
    {
        dim3 grid(1024, R_DIM);
        scatter_kernel<<<grid, 256>>>(edge_row, edge_col, edge_val, out, E);
    }
}